// round 2
// baseline (speedup 1.0000x reference)
#include <cuda_runtime.h>
#include <math.h>

// Problem constants (match reference)
#define P_L1 20
#define P_R1 70
#define P_L2 120
#define P_R2 170
#define NFACT 10
#define TT 200
#define NTRIALS 256
#define NCONFIGS 128
#define TWN 50
#define WIN 53          // window [L-1, R+1] inclusive
#define PLANE (NTRIALS * NCONFIGS)   // 32768

// JAX softplus: logaddexp(x, 0) = max(x,0) + log1p(exp(-|x|))
__device__ __forceinline__ float softplus_f(float x) {
    return fmaxf(x, 0.0f) + log1pf(expf(-fabsf(x)));
}

// ---------------------------------------------------------------------------
// Kernel 1: broadcast-fill the 100 static time columns per factor.
// 1000 blocks = (l, j) pairs; each fills one 32768-float plane with float4.
// ---------------------------------------------------------------------------
__global__ void __launch_bounds__(256) fill_kernel(
    const float* __restrict__ beta,
    float* __restrict__ out)
{
    int bid = blockIdx.x;          // 0..999
    int l = bid / 100;
    int j = bid - l * 100;         // 0..99 static-column index
    int t = (j < P_L1) ? j : ((j < 70) ? j + 50 : j + 100);

    float v = softplus_f(beta[l * TT + t]);
    float4 v4 = make_float4(v, v, v, v);

    float4* op = (float4*)(out + (size_t)(l * TT + t) * PLANE);
    const int n4 = PLANE / 4;      // 8192
    #pragma unroll 4
    for (int i = threadIdx.x; i < n4; i += 256)
        op[i] = v4;
}

// ---------------------------------------------------------------------------
// Kernel 2: warped regions. grid = 20 * 256 blocks (k, trial n),
// 128 threads = configs c. Each thread: compute warp params once, then loop
// 50 warped time steps with shared-memory window interpolation.
// ---------------------------------------------------------------------------
__global__ void __launch_bounds__(128) warp_kernel(
    const float* __restrict__ beta,
    const float* __restrict__ trial_off,   // [256,128,20]
    const float* __restrict__ cfg_off,     // [128,20]
    const float* __restrict__ timev,       // [200]
    float* __restrict__ out)
{
    const int bx  = blockIdx.x;
    const int k   = bx >> 8;                // 0..19  (seg*10 + l)
    const int n   = bx & 255;               // trial
    const int seg = (k >= NFACT) ? 1 : 0;
    const int l   = k - seg * NFACT;
    const int Ls  = seg ? P_L2 : P_L1;
    const int Rs  = seg ? P_R2 : P_R1;
    const int c   = threadIdx.x;            // config

    __shared__ float sf[WIN];
    __shared__ float s_peak;

    // softplus window [Ls-1, Rs+1]
    if (c < WIN)
        sf[c] = softplus_f(beta[l * TT + (Ls - 1) + c]);
    __syncthreads();

    // argmax over factors[:, Ls:Rs) == window idx 1..50 (first-max wins, like jnp.argmax)
    if (c == 0) {
        int am = 0;
        float best = sf[1];
        #pragma unroll 1
        for (int j = 1; j < 50; ++j) {
            float v = sf[1 + j];
            if (v > best) { best = v; am = j; }
        }
        s_peak = timev[Ls + am];
    }
    __syncthreads();

    const float dt   = timev[1] - timev[0];
    const float ll   = timev[Ls];
    const float rl   = timev[Rs];
    const float peak = s_peak;

    // s_new = peak + trial_offsets[n,c,k] + config_offsets[c,k], clamped
    float s = peak + trial_off[(n * NCONFIGS + c) * (2 * NFACT) + k]
                   + cfg_off[c * (2 * NFACT) + k];
    if (s <= ll) s = ll + dt;
    if (s >= rl) s = rl - dt;

    const float lsp    = s - ll;
    const float lslope = (peak - ll) / lsp;
    const float rslope = (peak - rl) / (s - rl);
    const float rdt    = 1.0f / dt;

    float* op = out + ((size_t)(l * TT + Ls) * NTRIALS + n) * NCONFIGS + c;

    #pragma unroll
    for (int tw = 0; tw < TWN; ++tw) {
        float lst = (float)tw * dt;
        float wt  = (lst < lsp) ? (lst * lslope + ll)
                                : ((lst - lsp) * rslope + peak);
        float wi = wt * rdt;
        float fl = floorf(wi);
        float cw = wi - fl;
        float fw = 1.0f - cw;
        int idx = (int)fl - (Ls - 1);
        idx = max(0, min(WIN - 2, idx));
        float v = fw * sf[idx] + cw * sf[idx + 1];
        op[(size_t)tw * PLANE] = v;
    }
}

// ---------------------------------------------------------------------------
extern "C" void kernel_launch(void* const* d_in, const int* in_sizes, int n_in,
                              void* d_out, int out_size)
{
    // Identify inputs by element count (all distinct): beta=2000,
    // trial_offsets=655360, config_offsets=2560, time=200.
    const float* beta = nullptr;
    const float* toff = nullptr;
    const float* coff = nullptr;
    const float* tim  = nullptr;
    for (int i = 0; i < n_in; ++i) {
        switch (in_sizes[i]) {
            case NFACT * TT:                         beta = (const float*)d_in[i]; break;
            case NTRIALS * NCONFIGS * 2 * NFACT:     toff = (const float*)d_in[i]; break;
            case NCONFIGS * 2 * NFACT:               coff = (const float*)d_in[i]; break;
            case TT:                                 tim  = (const float*)d_in[i]; break;
            default: break;
        }
    }
    float* out = (float*)d_out;

    fill_kernel<<<NFACT * 100, 256>>>(beta, out);
    warp_kernel<<<2 * NFACT * NTRIALS, 128>>>(beta, toff, coff, tim, out);
}

// round 4
// speedup vs baseline: 1.0494x; 1.0494x over previous
#include <cuda_runtime.h>
#include <math.h>

#define P_L1 20
#define P_R1 70
#define P_L2 120
#define P_R2 170
#define NFACT 10
#define TT 200
#define NTRIALS 256
#define NCONFIGS 128
#define TWN 50
#define WIN 53                        // softplus window [L-1, R+1]
#define PLANE (NTRIALS * NCONFIGS)    // 32768

// JAX softplus: max(x,0) + log1p(exp(-|x|))
__device__ __forceinline__ float softplus_f(float x) {
    return fmaxf(x, 0.0f) + log1pf(expf(-fabsf(x)));
}

// ---------------------------------------------------------------------------
// Fused kernel. Block groups of 7: sub 0..1 -> fill half-planes (2000 valid
// of 2048), sub 2..6 -> warp blocks (5120). 128 threads everywhere.
// ---------------------------------------------------------------------------
__global__ void __launch_bounds__(128) fused_kernel(
    const float* __restrict__ beta,
    const float* __restrict__ toff,    // [256,128,20]
    const float* __restrict__ coff,    // [128,20]
    const float* __restrict__ timev,   // [200]
    float* __restrict__ out)
{
    const int bid = blockIdx.x;
    const int grp = bid / 7;
    const int sub = bid - grp * 7;

    if (sub < 2) {
        // ---------------- fill path: broadcast softplus over half a plane ----
        int fid  = grp * 2 + sub;          // 0..2047, valid tasks 0..1999
        if (fid >= 2000) return;
        int p    = fid >> 1;               // plane 0..999 = (l, static col j)
        int half = fid & 1;
        int l = p / 100;
        int j = p - l * 100;
        int t = (j < P_L1) ? j : ((j < 70) ? j + 50 : j + 100);

        float v = softplus_f(beta[l * TT + t]);
        float4 v4 = make_float4(v, v, v, v);

        float4* op = (float4*)(out + (size_t)(l * TT + t) * PLANE)
                   + half * (PLANE / 8);
        #pragma unroll 4
        for (int i = threadIdx.x; i < PLANE / 8; i += 128)   // 4096 float4
            op[i] = v4;
        return;
    }

    // ------------------- warp path --------------------------------------
    const int wid = grp * 5 + (sub - 2);   // 0..5119
    const int k   = wid >> 8;              // 0..19 (seg*10 + l)
    const int n   = wid & 255;             // trial
    const int seg = (k >= NFACT) ? 1 : 0;
    const int l   = k - seg * NFACT;
    const int Ls  = seg ? P_L2 : P_L1;
    const int Rs  = seg ? P_R2 : P_R1;

    const int tid = threadIdx.x;
    const int q   = tid >> 5;              // tw phase 0..3
    const int c0  = (tid & 31) * 4;        // 4 consecutive configs per thread

    __shared__ float sf[WIN];
    __shared__ float s_peak;

    if (tid < WIN)
        sf[tid] = softplus_f(beta[l * TT + (Ls - 1) + tid]);
    __syncthreads();

    if (tid == 0) {                         // first-max argmax over window 1..50
        int am = 0;
        float best = sf[1];
        #pragma unroll 1
        for (int jj = 1; jj < 50; ++jj) {
            float v = sf[1 + jj];
            if (v > best) { best = v; am = jj; }
        }
        s_peak = timev[Ls + am];
    }
    __syncthreads();

    const float dt   = timev[1] - timev[0];
    const float rdt  = 1.0f / dt;
    const float ll   = timev[Ls];
    const float rl   = timev[Rs];
    const float peak = s_peak;
    const float b1   = ll * rdt;            // left-branch intercept (index space)

    // per-config warp params (index-space affine pieces)
    float t0[4], a1[4], a2[4], b2[4];
    #pragma unroll
    for (int j = 0; j < 4; ++j) {
        int c = c0 + j;
        float s = peak + toff[(n * NCONFIGS + c) * (2 * NFACT) + k]
                       + coff[c * (2 * NFACT) + k];
        if (s <= ll) s = ll + dt;
        if (s >= rl) s = rl - dt;
        float lsp    = s - ll;
        float lslope = (peak - ll) / lsp;
        float rslope = (peak - rl) / (s - rl);
        t0[j] = lsp * rdt;                          // branch point in tw units
        a1[j] = lslope;
        a2[j] = rslope;
        b2[j] = (peak - lsp * rslope) * rdt;        // right-branch intercept
    }

    // base float4 pointer at (l, Ls, n, c0)
    float4* op = (float4*)(out + ((size_t)(l * TT + Ls) * NTRIALS + n) * NCONFIGS + c0);

    #pragma unroll 1
    for (int tw = q; tw < TWN; tw += 4) {
        float twf = (float)tw;
        float4 v;
        float* vp = (float*)&v;
        #pragma unroll
        for (int j = 0; j < 4; ++j) {
            float wi = (twf < t0[j]) ? fmaf(twf, a1[j], b1)
                                     : fmaf(twf, a2[j], b2[j]);
            float fl = floorf(wi);
            float cw = wi - fl;
            int idx = (int)fl - (Ls - 1);
            idx = max(0, min(WIN - 2, idx));
            float f0 = sf[idx];
            float f1 = sf[idx + 1];
            vp[j] = fmaf(cw, f1 - f0, f0);
        }
        op[(size_t)tw * (PLANE / 4)] = v;
    }
}

// ---------------------------------------------------------------------------
extern "C" void kernel_launch(void* const* d_in, const int* in_sizes, int n_in,
                              void* d_out, int out_size)
{
    const float* beta = nullptr;
    const float* toff = nullptr;
    const float* coff = nullptr;
    const float* tim  = nullptr;
    for (int i = 0; i < n_in; ++i) {
        switch (in_sizes[i]) {
            case NFACT * TT:                      beta = (const float*)d_in[i]; break;
            case NTRIALS * NCONFIGS * 2 * NFACT:  toff = (const float*)d_in[i]; break;
            case NCONFIGS * 2 * NFACT:            coff = (const float*)d_in[i]; break;
            case TT:                              tim  = (const float*)d_in[i]; break;
            default: break;
        }
    }
    float* out = (float*)d_out;

    // 1024 groups * 7 = 7168 blocks: 2048 fill slots (2000 active) + 5120 warp
    fused_kernel<<<7168, 128>>>(beta, toff, coff, tim, out);
}

// round 5
// speedup vs baseline: 1.1919x; 1.1358x over previous
#include <cuda_runtime.h>
#include <math.h>

#define P_L1 20
#define P_R1 70
#define P_L2 120
#define P_R2 170
#define NFACT 10
#define TT 200
#define NTRIALS 256
#define NCONFIGS 128
#define TWN 50
#define WIN 53                        // softplus window [L-1, R+1]
#define PLANE (NTRIALS * NCONFIGS)    // 32768

#define N_FILL 4000                   // 1000 planes * 4 quarter-planes
#define N_WARP 5120                   // 20 k * 256 trials
#define GRP 16                        // 7 fill + 9 warp per group
#define NGRP 576                      // 576*7=4032 fill slots, 576*9=5184 warp slots

// JAX softplus: max(x,0) + log1p(exp(-|x|))
__device__ __forceinline__ float softplus_f(float x) {
    return fmaxf(x, 0.0f) + log1pf(expf(-fabsf(x)));
}

__global__ void __launch_bounds__(128) fused_kernel(
    const float* __restrict__ beta,
    const float* __restrict__ toff,    // [256,128,20]
    const float* __restrict__ coff,    // [128,20]
    const float* __restrict__ timev,   // [200]
    float* __restrict__ out)
{
    const int bid = blockIdx.x;
    const int grp = bid >> 4;
    const int sub = bid & 15;

    if (sub < 7) {
        // ---------------- fill path: quarter-plane broadcast ----------------
        int fid = grp * 7 + sub;           // 0..4031, valid 0..3999
        if (fid >= N_FILL) return;
        int p    = fid >> 2;               // plane 0..999 = (l, static col j)
        int quad = fid & 3;
        int l = p / 100;
        int j = p - l * 100;
        int t = (j < P_L1) ? j : ((j < 70) ? j + 50 : j + 100);

        float v = softplus_f(beta[l * TT + t]);
        float4 v4 = make_float4(v, v, v, v);

        float4* op = (float4*)(out + (size_t)(l * TT + t) * PLANE)
                   + quad * (PLANE / 16);
        #pragma unroll 4
        for (int i = threadIdx.x; i < PLANE / 16; i += 128)  // 2048 float4
            __stcs(&op[i], v4);
        return;
    }

    // ------------------- warp path --------------------------------------
    const int wid = grp * 9 + (sub - 7);   // 0..5183, valid 0..5119
    if (wid >= N_WARP) return;
    const int k   = wid >> 8;              // 0..19 (seg*10 + l)
    const int n   = wid & 255;             // trial
    const int seg = (k >= NFACT) ? 1 : 0;
    const int l   = k - seg * NFACT;
    const int Ls  = seg ? P_L2 : P_L1;
    const int Rs  = seg ? P_R2 : P_R1;

    const int tid  = threadIdx.x;
    const int lane = tid & 31;
    const int q    = tid >> 5;             // tw phase 0..3
    const int c0   = lane * 4;             // 4 consecutive configs per thread

    __shared__ float sf[WIN];

    if (tid < WIN)
        sf[tid] = softplus_f(beta[l * TT + (Ls - 1) + tid]);
    __syncthreads();

    // warp-parallel first-max argmax over sf[1..50] (each warp redundantly)
    float bv; int bi;
    {
        bv = sf[1 + lane]; bi = lane;      // lane 0..31 covers elems 0..31
        if (lane < 18) {                   // elems 32..49
            float v2 = sf[33 + lane];
            if (v2 > bv) { bv = v2; bi = lane + 32; }
        }
        #pragma unroll
        for (int off = 16; off > 0; off >>= 1) {
            float ov = __shfl_xor_sync(0xffffffffu, bv, off);
            int   oi = __shfl_xor_sync(0xffffffffu, bi, off);
            if (ov > bv || (ov == bv && oi < bi)) { bv = ov; bi = oi; }
        }
    }
    const float peak = timev[Ls + bi];

    const float dt  = timev[1] - timev[0];
    const float rdt = 1.0f / dt;
    const float ll  = timev[Ls];
    const float rl  = timev[Rs];
    const float b1  = ll * rdt;            // left-branch intercept (index space)

    // per-config warp params (index-space affine pieces)
    float t0[4], a1[4], a2[4], b2[4];
    #pragma unroll
    for (int j = 0; j < 4; ++j) {
        int c = c0 + j;
        float s = peak + toff[(n * NCONFIGS + c) * (2 * NFACT) + k]
                       + coff[c * (2 * NFACT) + k];
        if (s <= ll) s = ll + dt;
        if (s >= rl) s = rl - dt;
        float lsp    = s - ll;
        float lslope = (peak - ll) / lsp;
        float rslope = (peak - rl) / (s - rl);
        t0[j] = lsp * rdt;                          // branch point in tw units
        a1[j] = lslope;
        a2[j] = rslope;
        b2[j] = (peak - lsp * rslope) * rdt;        // right-branch intercept
    }

    // base float4 pointer at (l, Ls, n, c0)
    float4* op = (float4*)(out + ((size_t)(l * TT + Ls) * NTRIALS + n) * NCONFIGS + c0);

    #pragma unroll 1
    for (int tw = q; tw < TWN; tw += 4) {
        float twf = (float)tw;
        float4 v;
        float* vp = (float*)&v;
        #pragma unroll
        for (int j = 0; j < 4; ++j) {
            float wi = (twf < t0[j]) ? fmaf(twf, a1[j], b1)
                                     : fmaf(twf, a2[j], b2[j]);
            float fl = floorf(wi);
            float cw = wi - fl;
            int idx = (int)fl - (Ls - 1);
            idx = max(0, min(WIN - 2, idx));
            float f0 = sf[idx];
            float f1 = sf[idx + 1];
            vp[j] = fmaf(cw, f1 - f0, f0);
        }
        __stcs(&op[(size_t)tw * (PLANE / 4)], v);
    }
}

// ---------------------------------------------------------------------------
extern "C" void kernel_launch(void* const* d_in, const int* in_sizes, int n_in,
                              void* d_out, int out_size)
{
    const float* beta = nullptr;
    const float* toff = nullptr;
    const float* coff = nullptr;
    const float* tim  = nullptr;
    for (int i = 0; i < n_in; ++i) {
        switch (in_sizes[i]) {
            case NFACT * TT:                      beta = (const float*)d_in[i]; break;
            case NTRIALS * NCONFIGS * 2 * NFACT:  toff = (const float*)d_in[i]; break;
            case NCONFIGS * 2 * NFACT:            coff = (const float*)d_in[i]; break;
            case TT:                              tim  = (const float*)d_in[i]; break;
            default: break;
        }
    }
    float* out = (float*)d_out;

    fused_kernel<<<NGRP * GRP, 128>>>(beta, toff, coff, tim, out);
}